// round 2
// baseline (speedup 1.0000x reference)
#include <cuda_runtime.h>
#include <math.h>

#define VOCAB 50000
#define E 128
#define H 128
#define B 256
#define T 2048

// Device scratch (sanctioned: __device__ globals, no allocation)
__device__ float g_X0[VOCAB * H];   // emb @ W_ih[0] + b0, per vocab id
__device__ int   g_order[B];        // batch rows sorted by length, descending

// ---------------------------------------------------------------------------
// Kernel A: rank-sort rows by length (descending, stable). 1 CTA, 256 threads.
// ---------------------------------------------------------------------------
__global__ void sort_kernel(const int* __restrict__ lengths) {
    __shared__ int s_len[B];
    int i = threadIdx.x;
    s_len[i] = lengths[i];
    __syncthreads();
    int li = s_len[i];
    int rank = 0;
    for (int jj = 0; jj < B; jj++) {
        int lj = s_len[jj];
        rank += (lj > li) || (lj == li && jj < i);
    }
    g_order[rank] = i;
}

// ---------------------------------------------------------------------------
// Kernel B: X0[v][j] = b0[j] + sum_k emb[v][k] * W_ih0[k][j]
// 256 threads = (k-half, column j); W_ih0 column halves in registers (64 ea).
// Grid-stride over vocab rows. Smem: emb row broadcast + 2x128 partials.
// ---------------------------------------------------------------------------
__global__ void __launch_bounds__(256, 1)
x0_kernel(const float* __restrict__ emb,
          const float* __restrict__ W_ih,
          const float* __restrict__ b) {
    __shared__ float embs[H];
    __shared__ float part[2 * H];

    int tid   = threadIdx.x;
    int half  = tid >> 7;
    int j     = tid & 127;
    int kbase = half * 64;

    float w[64];
    #pragma unroll
    for (int kk = 0; kk < 64; kk++)
        w[kk] = W_ih[(kbase + kk) * H + j];   // layer 0 slice
    float b0 = b[j];

    for (int r = blockIdx.x; r < VOCAB; r += gridDim.x) {
        if (tid < H) embs[tid] = emb[r * E + tid];
        __syncthreads();
        float a0 = 0.f, a1 = 0.f, a2 = 0.f, a3 = 0.f;
        #pragma unroll
        for (int kk = 0; kk < 64; kk += 4) {
            float4 ev = *(const float4*)&embs[kbase + kk];
            a0 += ev.x * w[kk + 0];
            a1 += ev.y * w[kk + 1];
            a2 += ev.z * w[kk + 2];
            a3 += ev.w * w[kk + 3];
        }
        part[tid] = (a0 + a1) + (a2 + a3);
        __syncthreads();
        if (tid < H) g_X0[r * H + j] = b0 + part[j] + part[H + j];
        __syncthreads();   // protect embs/part before next row overwrites
    }
}

// ---------------------------------------------------------------------------
// Kernel C: persistent per-row RNN.
// 256 CTAs (one batch row each, longest rows first), 256 threads:
//   thread = (half, j): half = k-range [64*half, 64*half+64), j = output column.
// Weights (W_hh0, W_ih1, W_hh1 columns) live in registers: 3*64 = 192 floats.
// Per step: 3 barriers, layer-0 input is a prefetched gather from g_X0.
// ---------------------------------------------------------------------------
__global__ void __launch_bounds__(256, 1)
rnn_kernel(const int* __restrict__ x, const int* __restrict__ lengths,
           const float* __restrict__ W_ih, const float* __restrict__ W_hh,
           const float* __restrict__ b, const float* __restrict__ cls_w,
           const float* __restrict__ cls_b, float* __restrict__ out) {
    __shared__ int   xrow[T];
    __shared__ float h0s[H];
    __shared__ float h1s[H];
    __shared__ float part0[2 * H];
    __shared__ float part1[2 * H];

    int tid   = threadIdx.x;
    int half  = tid >> 7;        // 0 or 1
    int j     = tid & 127;       // output column
    int kbase = half * 64;

    int row = g_order[blockIdx.x];
    int len = lengths[row];

    // Load this thread's weight columns into registers (constant indices after
    // full unroll -> register arrays, no local memory).
    float w0[64], w1[64], w2[64];
    #pragma unroll
    for (int kk = 0; kk < 64; kk++) {
        int k = kbase + kk;
        w0[kk] = W_hh[0 * H * H + k * H + j];   // W_hh layer 0
        w1[kk] = W_ih[1 * H * H + k * H + j];   // W_ih layer 1
        w2[kk] = W_hh[1 * H * H + k * H + j];   // W_hh layer 1
    }
    float b1v = b[H + j];

    // Stage token ids for this row into smem (8 KB).
    for (int i = tid; i < T; i += 256) xrow[i] = x[row * T + i];
    if (tid < H) { h0s[tid] = 0.f; h1s[tid] = 0.f; }
    __syncthreads();

    float x0cur = 0.f, x0nxt = 0.f;
    if (tid < H) x0cur = g_X0[xrow[0] * H + j];

    for (int t = 0; t < len; t++) {
        // Prefetch next step's projected input (latency hidden by the matmuls).
        int tn = (t + 1 < len) ? (t + 1) : t;
        if (tid < H) x0nxt = g_X0[xrow[tn] * H + j];

        // ---- layer 0 recurrent partial: h0_prev @ W_hh0 (this k-half) ----
        float a0 = 0.f, a1 = 0.f, a2 = 0.f, a3 = 0.f;
        #pragma unroll
        for (int kk = 0; kk < 64; kk += 4) {
            float4 hv = *(const float4*)&h0s[kbase + kk];
            a0 += hv.x * w0[kk + 0];
            a1 += hv.y * w0[kk + 1];
            a2 += hv.z * w0[kk + 2];
            a3 += hv.w * w0[kk + 3];
        }
        part0[tid] = (a0 + a1) + (a2 + a3);
        __syncthreads();                         // (1) partials0 complete

        if (tid < H) {
            float a = x0cur + part0[j] + part0[H + j];   // b0 folded into X0
            h0s[j] = tanhf(a);
        }
        __syncthreads();                         // (2) new h0 visible

        // ---- layer 1: h0_new @ W_ih1 + h1_prev @ W_hh1 (this k-half) ----
        a0 = a1 = a2 = a3 = 0.f;
        #pragma unroll
        for (int kk = 0; kk < 64; kk += 4) {
            float4 hv = *(const float4*)&h0s[kbase + kk];
            float4 gv = *(const float4*)&h1s[kbase + kk];
            a0 += hv.x * w1[kk + 0] + gv.x * w2[kk + 0];
            a1 += hv.y * w1[kk + 1] + gv.y * w2[kk + 1];
            a2 += hv.z * w1[kk + 2] + gv.z * w2[kk + 2];
            a3 += hv.w * w1[kk + 3] + gv.w * w2[kk + 3];
        }
        part1[tid] = (a0 + a1) + (a2 + a3);
        __syncthreads();                         // (3) partials1 complete

        if (tid < H) {
            float a = b1v + part1[j] + part1[H + j];
            h1s[j] = tanhf(a);
            // No 4th barrier: barrier (1) of the next iteration orders this
            // h1s write before the next layer-1 matmul reads it, and nothing
            // between touches h1s or part1.
        }
        x0cur = x0nxt;
    }
    __syncthreads();   // final h1s visible to classifier warp

    // ---- classifier: sigmoid(h1 . cls_w + cls_b) ----
    if (tid < 32) {
        float v = 0.f;
        #pragma unroll
        for (int m = 0; m < 4; m++) {
            int jj = tid + 32 * m;
            v += h1s[jj] * cls_w[jj];
        }
        #pragma unroll
        for (int off = 16; off; off >>= 1)
            v += __shfl_xor_sync(0xffffffffu, v, off);
        if (tid == 0) out[row] = 1.f / (1.f + expf(-(v + cls_b[0])));
    }
}

// ---------------------------------------------------------------------------
extern "C" void kernel_launch(void* const* d_in, const int* in_sizes, int n_in,
                              void* d_out, int out_size) {
    const int*   x       = (const int*)d_in[0];
    const int*   lengths = (const int*)d_in[1];
    const float* emb     = (const float*)d_in[2];
    const float* W_ih    = (const float*)d_in[3];
    const float* W_hh    = (const float*)d_in[4];
    const float* b       = (const float*)d_in[5];
    const float* cls_w   = (const float*)d_in[6];
    const float* cls_b   = (const float*)d_in[7];
    float*       out     = (float*)d_out;

    sort_kernel<<<1, B>>>(lengths);
    x0_kernel<<<1024, 256>>>(emb, W_ih, b);
    rnn_kernel<<<B, 256>>>(x, lengths, W_ih, W_hh, b, cls_w, cls_b, out);
}

// round 4
// speedup vs baseline: 1.4972x; 1.4972x over previous
#include <cuda_runtime.h>
#include <math.h>

#define VOCAB 50000
#define E 128
#define H 128
#define B 256
#define T 2048

typedef unsigned long long ull;

// Packed f32x2 FMA (Blackwell): d.lo=a.lo*b.lo+c.lo, d.hi=a.hi*b.hi+c.hi
#define FMA2(d, a, b, c) \
    asm("fma.rn.f32x2 %0, %1, %2, %3;" : "=l"(d) : "l"(a), "l"(b), "l"(c))
#define PACK2(d, lo, hi) \
    asm("mov.b64 %0, {%1, %2};" : "=l"(d) : "f"(lo), "f"(hi))
#define UNPACK2(lo, hi, v) \
    asm("mov.b64 {%0, %1}, %2;" : "=f"(lo), "=f"(hi) : "l"(v))

// Device scratch (sanctioned: __device__ globals, no allocation)
__device__ float g_X0[VOCAB * H];   // emb @ W_ih[0] + b0, per vocab id
__device__ int   g_order[B];        // batch rows sorted by length, descending

// ---------------------------------------------------------------------------
// Kernel A: rank-sort rows by length (descending, stable). 1 CTA, 256 threads.
// ---------------------------------------------------------------------------
__global__ void sort_kernel(const int* __restrict__ lengths) {
    __shared__ int s_len[B];
    int i = threadIdx.x;
    s_len[i] = lengths[i];
    __syncthreads();
    int li = s_len[i];
    int rank = 0;
    for (int jj = 0; jj < B; jj++) {
        int lj = s_len[jj];
        rank += (lj > li) || (lj == li && jj < i);
    }
    g_order[rank] = i;
}

// ---------------------------------------------------------------------------
// Kernel B: X0[v][j] = b0[j] + sum_k emb[v][k] * W_ih0[k][j]   (FFMA2 packed)
// 256 threads = (k-half, column j); weight k-pairs packed in 32 ull regs.
// ---------------------------------------------------------------------------
__global__ void __launch_bounds__(256)
x0_kernel(const float* __restrict__ emb,
          const float* __restrict__ W_ih,
          const float* __restrict__ b) {
    __shared__ __align__(16) float embs[H];
    __shared__ float part[2 * H];

    int tid   = threadIdx.x;
    int half  = tid >> 7;
    int j     = tid & 127;
    int kbase = half * 64;

    ull w[32];
    #pragma unroll
    for (int kk = 0; kk < 32; kk++) {
        int k = kbase + 2 * kk;
        PACK2(w[kk], W_ih[k * H + j], W_ih[(k + 1) * H + j]);
    }
    float b0 = b[j];

    for (int r = blockIdx.x; r < VOCAB; r += gridDim.x) {
        if (tid < H) embs[tid] = emb[r * E + tid];
        __syncthreads();
        ull acc = 0;
        #pragma unroll
        for (int i = 0; i < 16; i++) {
            ulonglong2 ev = *(const ulonglong2*)&embs[kbase + 4 * i];
            FMA2(acc, ev.x, w[2 * i], acc);
            FMA2(acc, ev.y, w[2 * i + 1], acc);
        }
        float lo, hi;
        UNPACK2(lo, hi, acc);
        part[tid] = lo + hi;
        __syncthreads();
        if (tid < H) g_X0[r * H + j] = b0 + part[j] + part[H + j];
        __syncthreads();
    }
}

// ---------------------------------------------------------------------------
// Kernel C: persistent per-row RNN, cross-layer pipelined.
// 256 CTAs (one row each, longest first), 256 threads = 8 warps.
// Lane layout: warp w, lane l -> column j = 16*w + (l&15), k-half = l>>4.
// Superstep t computes BOTH h1(t) and h0(t+1) from {h0(t), h1(t-1)}:
//   h1(t)   = tanh(b1 + W_ih1 h0(t) + W_hh1 h1(t-1))
//   h0(t+1) = tanh(X0[tok[t+1]] + W_hh0 h0(t))
// Cross-half reduce via shfl.bfly(16); h double-buffered -> 1 barrier/step.
// ---------------------------------------------------------------------------
__global__ void __launch_bounds__(256, 1)
rnn_kernel(const int* __restrict__ x, const int* __restrict__ lengths,
           const float* __restrict__ W_ih, const float* __restrict__ W_hh,
           const float* __restrict__ b, const float* __restrict__ cls_w,
           const float* __restrict__ cls_b, float* __restrict__ out) {
    __shared__ int xrow[T];
    __shared__ __align__(16) float h0s[2][H];
    __shared__ __align__(16) float h1s[2][H];

    int tid   = threadIdx.x;
    int warp  = tid >> 5;
    int lane  = tid & 31;
    int j     = warp * 16 + (lane & 15);
    int half  = lane >> 4;
    int kbase = half * 64;

    int row = g_order[blockIdx.x];
    int len = lengths[row];

    // Pre-packed weight k-pair columns in registers: 3 x 32 ull.
    ull w0p[32], w1p[32], w2p[32];
    #pragma unroll
    for (int kk = 0; kk < 32; kk++) {
        int k = kbase + 2 * kk;
        PACK2(w0p[kk], W_hh[k * H + j],           W_hh[(k + 1) * H + j]);           // W_hh0
        PACK2(w1p[kk], W_ih[H * H + k * H + j],   W_ih[H * H + (k + 1) * H + j]);   // W_ih1
        PACK2(w2p[kk], W_hh[H * H + k * H + j],   W_hh[H * H + (k + 1) * H + j]);   // W_hh1
    }
    float b1v = b[H + j];

    // Stage token ids for this row into smem (8 KB).
    for (int i = tid; i < T; i += 256) xrow[i] = x[row * T + i];
    __syncthreads();

    // Prologue: h0(0) = tanh(X0[tok0]) (b0 folded into X0, h_init = 0); h1(-1)=0.
    if (half == 0) h0s[0][j] = tanhf(g_X0[xrow[0] * H + j]);
    else           h1s[0][j] = 0.f;
    float x0cur = 0.f, x0nxt = 0.f;
    if (half == 0) x0cur = g_X0[xrow[(len > 1) ? 1 : 0] * H + j];
    __syncthreads();

    for (int t = 0; t < len; t++) {
        int p = t & 1;
        const float* hr0 = &h0s[p][kbase];
        const float* hr1 = &h1s[p][kbase];

        // Prefetch X0 for superstep t+1 (needs tok[t+2]).
        if (half == 0) {
            int tn = t + 2;
            if (tn > len - 1) tn = len - 1;
            x0nxt = g_X0[xrow[tn] * H + j];
        }

        // Three matmul partials over this thread's k-half (FFMA2-packed).
        ull acc0 = 0, acc1 = 0, acc2 = 0;
        #pragma unroll
        for (int i = 0; i < 16; i++) {
            ulonglong2 hp = *(const ulonglong2*)(hr0 + 4 * i);
            FMA2(acc0, hp.x, w0p[2 * i],     acc0);
            FMA2(acc0, hp.y, w0p[2 * i + 1], acc0);
            FMA2(acc1, hp.x, w1p[2 * i],     acc1);
            FMA2(acc1, hp.y, w1p[2 * i + 1], acc1);
            ulonglong2 gp = *(const ulonglong2*)(hr1 + 4 * i);
            FMA2(acc2, gp.x, w2p[2 * i],     acc2);
            FMA2(acc2, gp.y, w2p[2 * i + 1], acc2);
        }

        // Reduce: packed lanes, then across k-halves (bfly 16).
        float lo, hi, s0, s1, s2;
        UNPACK2(lo, hi, acc0); s0 = lo + hi;
        UNPACK2(lo, hi, acc1); s1 = lo + hi;
        UNPACK2(lo, hi, acc2); s2 = lo + hi;
        s0 += __shfl_xor_sync(0xffffffffu, s0, 16);
        s1 += __shfl_xor_sync(0xffffffffu, s1, 16);
        s2 += __shfl_xor_sync(0xffffffffu, s2, 16);

        // half 0 produces h0(t+1); half 1 produces h1(t).
        float argv = half ? (b1v + s1 + s2) : (x0cur + s0);
        float hv = tanhf(argv);

        // Double-buffered write: no WAR hazard, single barrier per step.
        float* dst = half ? &h1s[p ^ 1][0] : &h0s[p ^ 1][0];
        dst[j] = hv;
        __syncthreads();

        x0cur = x0nxt;
    }

    // ---- classifier: sigmoid(h1_final . cls_w + cls_b) ----
    const float* h1f = h1s[len & 1];
    if (tid < 32) {
        float v = 0.f;
        #pragma unroll
        for (int m = 0; m < 4; m++) {
            int jj = tid + 32 * m;
            v += h1f[jj] * cls_w[jj];
        }
        #pragma unroll
        for (int off = 16; off; off >>= 1)
            v += __shfl_xor_sync(0xffffffffu, v, off);
        if (tid == 0) out[row] = 1.f / (1.f + expf(-(v + cls_b[0])));
    }
}

// ---------------------------------------------------------------------------
extern "C" void kernel_launch(void* const* d_in, const int* in_sizes, int n_in,
                              void* d_out, int out_size) {
    const int*   x       = (const int*)d_in[0];
    const int*   lengths = (const int*)d_in[1];
    const float* emb     = (const float*)d_in[2];
    const float* W_ih    = (const float*)d_in[3];
    const float* W_hh    = (const float*)d_in[4];
    const float* b       = (const float*)d_in[5];
    const float* cls_w   = (const float*)d_in[6];
    const float* cls_b   = (const float*)d_in[7];
    float*       out     = (float*)d_out;

    sort_kernel<<<1, B>>>(lengths);
    x0_kernel<<<1024, 256>>>(emb, W_ih, b);
    rnn_kernel<<<B, 256>>>(x, lengths, W_ih, W_hh, b, cls_w, cls_b, out);
}